// round 12
// baseline (speedup 1.0000x reference)
#include <cuda_runtime.h>
#include <cuda_bf16.h>
#include <cstdint>

#define EPSV 1e-5f

// ------------------------- scratch (global, static) ------------------------
__device__ float g_conv1[128 * 32768];
__device__ float g_qkv [256 * 32768];
__device__ float g_outb[2 * 512 * 128 * 64];
__device__ float g_co  [256 * 32768];
__device__ float g_part[512 * 24 * 2];
__device__ float g_partG[512 * 256 * 2];
__device__ float g_partA[4096 * 64];
__device__ float g_sum [512];
__device__ float g_scA [24];
__device__ float g_shA [24];
__device__ __nv_bfloat16 g_x1h[128 * 32768], g_x1l[128 * 32768];
__device__ __nv_bfloat16 g_x2h[128 * 32768], g_x2l[128 * 32768];
__device__ __nv_bfloat16 g_x3h[128 * 32768], g_x3l[128 * 32768];

// ========================= helpers ==========================================
__device__ __forceinline__ uint32_t smem_u32(const void* p) {
    uint32_t a;
    asm("{ .reg .u64 t; cvta.to.shared.u64 t, %1; cvt.u32.u64 %0, t; }" : "=r"(a) : "l"(p));
    return a;
}
__device__ __forceinline__ void ldsm_x4(uint32_t (&r)[4], uint32_t addr) {
    asm volatile("ldmatrix.sync.aligned.m8n8.x4.shared.b16 {%0,%1,%2,%3}, [%4];"
                 : "=r"(r[0]), "=r"(r[1]), "=r"(r[2]), "=r"(r[3]) : "r"(addr));
}
__device__ __forceinline__ void ldsm_x4t(uint32_t (&r)[4], uint32_t addr) {
    asm volatile("ldmatrix.sync.aligned.m8n8.x4.trans.shared.b16 {%0,%1,%2,%3}, [%4];"
                 : "=r"(r[0]), "=r"(r[1]), "=r"(r[2]), "=r"(r[3]) : "r"(addr));
}
__device__ __forceinline__ void mma_bf16(float (&c)[4], const uint32_t (&a)[4],
                                         uint32_t b0, uint32_t b1) {
    asm volatile("mma.sync.aligned.m16n8k16.row.col.f32.bf16.bf16.f32 "
                 "{%0,%1,%2,%3}, {%4,%5,%6,%7}, {%8,%9}, {%0,%1,%2,%3};"
                 : "+f"(c[0]), "+f"(c[1]), "+f"(c[2]), "+f"(c[3])
                 : "r"(a[0]), "r"(a[1]), "r"(a[2]), "r"(a[3]), "r"(b0), "r"(b1));
}
__device__ __forceinline__ uint32_t pack_hilo(float x, float y, uint32_t& lo) {
    __nv_bfloat162 h = __floats2bfloat162_rn(x, y);
    float rx = x - __bfloat162float(h.x);
    float ry = y - __bfloat162float(h.y);
    __nv_bfloat162 l = __floats2bfloat162_rn(rx, ry);
    lo = *reinterpret_cast<uint32_t*>(&l);
    return *reinterpret_cast<uint32_t*>(&h);
}
__device__ __forceinline__ void cp16(uint32_t smem_addr, const void* gptr) {
    asm volatile("cp.async.cg.shared.global [%0], [%1], 16;"
                 :: "r"(smem_addr), "l"(gptr) : "memory");
}
#define CP_COMMIT() asm volatile("cp.async.commit_group;" ::: "memory")
#define CP_WAIT0()  asm volatile("cp.async.wait_group 0;" ::: "memory")

// packed fp32x2 FMA (Blackwell FFMA2): c = a*b + c, elementwise on 2 lanes
__device__ __forceinline__ void ffma2(float2& c, float2 a, float2 b) {
    asm("fma.rn.f32x2 %0, %1, %2, %0;"
        : "+l"(reinterpret_cast<unsigned long long&>(c))
        : "l"(reinterpret_cast<unsigned long long&>(a)),
          "l"(reinterpret_cast<unsigned long long&>(b)));
}

// ============== GEMM A (fp32 operands, in-kernel split) — conv_in ===========
template <int KDIM, int MODE, bool STATS>
__global__ void __launch_bounds__(128) gemm_mma(const float* __restrict__ A,
                                                const float* __restrict__ Bm,
                                                float* __restrict__ C,
                                                float* __restrict__ part) {
    constexpr uint32_t AL_B = 128 * 72 * 2;
    constexpr uint32_t BH_B = 2 * AL_B;
    constexpr uint32_t BL_B = BH_B + 64 * 136 * 2;

    extern __shared__ __align__(16) char smem[];
    __nv_bfloat16* sAh = (__nv_bfloat16*)smem;
    __nv_bfloat16* sAl = (__nv_bfloat16*)(smem + AL_B);
    __nv_bfloat16* sBh = (__nv_bfloat16*)(smem + BH_B);
    __nv_bfloat16* sBl = (__nv_bfloat16*)(smem + BL_B);
    uint32_t sbase = smem_u32(smem);

    int tid = threadIdx.x, lane = tid & 31, wid = tid >> 5;
    int warp_m = wid & 1, warp_n = wid >> 1;
    int bn = blockIdx.x * 128;
    int bm = blockIdx.y * 128;

    int a_row_off = ((lane >> 3) & 1) * 8 + (lane & 7);
    int a_k_off   = (lane >> 4) * 8;
    int b_k_off   = a_row_off;
    int b_n_off   = a_k_off;

    float acc[4][8][4];
#pragma unroll
    for (int mt = 0; mt < 4; mt++)
#pragma unroll
        for (int nt = 0; nt < 8; nt++)
#pragma unroll
            for (int r = 0; r < 4; r++) acc[mt][nt][r] = 0.f;

    for (int k0 = 0; k0 < KDIM; k0 += 64) {
#pragma unroll
        for (int it = 0; it < 16; it++) {
            int flat = it * 128 + tid;
            int row = flat >> 4, c4 = (flat & 15) << 2;
            float4 v = *(const float4*)(A + (size_t)(bm + row) * KDIM + k0 + c4);
            uint32_t l0, l1;
            uint32_t h0 = pack_hilo(v.x, v.y, l0);
            uint32_t h1 = pack_hilo(v.z, v.w, l1);
            uint32_t off = (uint32_t)(row * 72 + c4);
            *(uint2*)(sAh + off) = make_uint2(h0, h1);
            *(uint2*)(sAl + off) = make_uint2(l0, l1);
        }
#pragma unroll
        for (int it = 0; it < 16; it++) {
            int flat = it * 128 + tid;
            int row = flat >> 5, c4 = (flat & 31) << 2;
            const float* br = (MODE == 0)
                ? Bm + (size_t)(k0 + row) * 32768 + bn + c4
                : Bm + ((size_t)(bn >> 12) * KDIM + k0 + row) * 4096 + (bn & 4095) + c4;
            float4 v = *(const float4*)br;
            uint32_t l0, l1;
            uint32_t h0 = pack_hilo(v.x, v.y, l0);
            uint32_t h1 = pack_hilo(v.z, v.w, l1);
            uint32_t off = (uint32_t)(row * 136 + c4);
            *(uint2*)(sBh + off) = make_uint2(h0, h1);
            *(uint2*)(sBl + off) = make_uint2(l0, l1);
        }
        __syncthreads();

#pragma unroll
        for (int ks = 0; ks < 4; ks++) {
            uint32_t ah[4][4], al[4][4];
#pragma unroll
            for (int mt = 0; mt < 4; mt++) {
                uint32_t addr = sbase +
                    (uint32_t)(((warp_m * 64 + mt * 16 + a_row_off) * 72 + ks * 16 + a_k_off) * 2);
                ldsm_x4(ah[mt], addr);
                ldsm_x4(al[mt], addr + AL_B);
            }
#pragma unroll
            for (int gi = 0; gi < 4; gi++) {
                uint32_t bh[4], bl[4];
                uint32_t addr = sbase + BH_B +
                    (uint32_t)(((ks * 16 + b_k_off) * 136 + warp_n * 64 + gi * 16 + b_n_off) * 2);
                ldsm_x4t(bh, addr);
                ldsm_x4t(bl, addr + (BL_B - BH_B));
#pragma unroll
                for (int mt = 0; mt < 4; mt++)
#pragma unroll
                    for (int sub = 0; sub < 2; sub++) {
                        int nt = gi * 2 + sub;
                        mma_bf16(acc[mt][nt], ah[mt], bh[2 * sub], bh[2 * sub + 1]);
                        mma_bf16(acc[mt][nt], ah[mt], bl[2 * sub], bl[2 * sub + 1]);
                        mma_bf16(acc[mt][nt], al[mt], bh[2 * sub], bh[2 * sub + 1]);
                    }
            }
        }
        __syncthreads();
    }

    int g = lane >> 2, t = lane & 3;
#pragma unroll
    for (int mt = 0; mt < 4; mt++) {
        int r0 = bm + warp_m * 64 + mt * 16 + g;
#pragma unroll
        for (int nt = 0; nt < 8; nt++) {
            int col = bn + warp_n * 64 + nt * 8 + 2 * t;
            *(float2*)(C + (size_t)r0 * 32768 + col) = make_float2(acc[mt][nt][0], acc[mt][nt][1]);
            *(float2*)(C + (size_t)(r0 + 8) * 32768 + col) = make_float2(acc[mt][nt][2], acc[mt][nt][3]);
        }
    }

    if (STATS) {
        int CH = gridDim.y * 128;
#pragma unroll
        for (int mt = 0; mt < 4; mt++)
#pragma unroll
            for (int half = 0; half < 2; half++) {
                float s = 0.f, ss = 0.f;
#pragma unroll
                for (int nt = 0; nt < 8; nt++) {
                    float v0 = acc[mt][nt][half * 2], v1 = acc[mt][nt][half * 2 + 1];
                    s += v0 + v1;
                    ss = fmaf(v0, v0, ss); ss = fmaf(v1, v1, ss);
                }
                s  += __shfl_xor_sync(0xffffffffu, s, 1);
                s  += __shfl_xor_sync(0xffffffffu, s, 2);
                ss += __shfl_xor_sync(0xffffffffu, ss, 1);
                ss += __shfl_xor_sync(0xffffffffu, ss, 2);
                if (t == 0) {
                    int row = bm + warp_m * 64 + mt * 16 + half * 8 + g;
                    float* dst = part + ((size_t)(blockIdx.x * 2 + warp_n) * CH + row) * 2;
                    dst[0] = s; dst[1] = ss;
                }
            }
    }
}

// ===== GEMM B: A fp32 weights split in prologue (full-K resident), B bf16 ===
// smem: Ah[128][136] Al[128][136] (69632 B) + B 2-stage (2 x 2 x 8704 B)
template <int MODE, bool STATS>
__global__ void __launch_bounds__(128) gemm_ca(const float* __restrict__ A,
                                               const __nv_bfloat16* __restrict__ Bhg,
                                               const __nv_bfloat16* __restrict__ Blg,
                                               float* __restrict__ C,
                                               float* __restrict__ part) {
    constexpr int KDIM = 128;
    constexpr uint32_t A_SZ   = 128 * 136 * 2;        // 34816 per split
    constexpr uint32_t B_SZ   = 32 * 136 * 2;         // 8704
    constexpr uint32_t BSTAGE = 2 * B_SZ;             // 17408
    constexpr uint32_t B_OFF  = 2 * A_SZ;             // 69632

    extern __shared__ __align__(16) char smem[];
    __nv_bfloat16* sAh = (__nv_bfloat16*)smem;
    __nv_bfloat16* sAl = (__nv_bfloat16*)(smem + A_SZ);
    uint32_t sbase = smem_u32(smem);

    int tid = threadIdx.x, lane = tid & 31, wid = tid >> 5;
    int warp_m = wid & 1, warp_n = wid >> 1;
    int bn = blockIdx.x * 128;
    int bm = blockIdx.y * 128;

    int a_row_off = ((lane >> 3) & 1) * 8 + (lane & 7);
    int a_k_off   = (lane >> 4) * 8;
    int b_k_off   = a_row_off;
    int b_n_off   = a_k_off;

    float acc[4][8][4];
#pragma unroll
    for (int mt = 0; mt < 4; mt++)
#pragma unroll
        for (int nt = 0; nt < 8; nt++)
#pragma unroll
            for (int r = 0; r < 4; r++) acc[mt][nt][r] = 0.f;

    auto issue = [&](int c) {
        uint32_t st = sbase + B_OFF + (uint32_t)(c & 1) * BSTAGE;
        int k0 = c * 32;
#pragma unroll
        for (int it = 0; it < 4; it++) {
            int flat = it * 128 + tid;
            int row = flat >> 4, seg = (flat & 15) * 8;
            size_t goff = (MODE == 0)
                ? (size_t)(k0 + row) * 32768 + bn + seg
                : ((size_t)(bn >> 12) * KDIM + k0 + row) * 4096 + (bn & 4095) + seg;
            uint32_t soff = (uint32_t)(row * 136 + seg) * 2;
            cp16(st + soff, Bhg + goff);
            cp16(st + B_SZ + soff, Blg + goff);
        }
        CP_COMMIT();
    };

    issue(0);
    // A prologue: load 128x128 fp32 weights, split -> smem (full K resident)
#pragma unroll
    for (int it = 0; it < 32; it++) {
        int flat = it * 128 + tid;                  // 4096 float4
        int row = flat >> 5, c4 = (flat & 31) << 2;
        float4 v = *(const float4*)(A + (size_t)(bm + row) * KDIM + c4);
        uint32_t l0, l1;
        uint32_t h0 = pack_hilo(v.x, v.y, l0);
        uint32_t h1 = pack_hilo(v.z, v.w, l1);
        uint32_t off = (uint32_t)(row * 136 + c4);
        *(uint2*)(sAh + off) = make_uint2(h0, h1);
        *(uint2*)(sAl + off) = make_uint2(l0, l1);
    }
    CP_WAIT0();
    __syncthreads();

#pragma unroll
    for (int c = 0; c < 4; c++) {
        if (c < 3) issue(c + 1);
        uint32_t stB = sbase + B_OFF + (uint32_t)(c & 1) * BSTAGE;
#pragma unroll
        for (int ks = 0; ks < 2; ks++) {
            uint32_t ah[4][4], al[4][4];
#pragma unroll
            for (int mt = 0; mt < 4; mt++) {
                uint32_t addr = sbase +
                    (uint32_t)(((warp_m * 64 + mt * 16 + a_row_off) * 136 + c * 32 + ks * 16 + a_k_off) * 2);
                ldsm_x4(ah[mt], addr);
                ldsm_x4(al[mt], addr + A_SZ);
            }
#pragma unroll
            for (int gi = 0; gi < 4; gi++) {
                uint32_t bh[4], bl[4];
                uint32_t addr = stB +
                    (uint32_t)(((ks * 16 + b_k_off) * 136 + warp_n * 64 + gi * 16 + b_n_off) * 2);
                ldsm_x4t(bh, addr);
                ldsm_x4t(bl, addr + B_SZ);
#pragma unroll
                for (int mt = 0; mt < 4; mt++)
#pragma unroll
                    for (int sub = 0; sub < 2; sub++) {
                        int nt = gi * 2 + sub;
                        mma_bf16(acc[mt][nt], ah[mt], bh[2 * sub], bh[2 * sub + 1]);
                        mma_bf16(acc[mt][nt], ah[mt], bl[2 * sub], bl[2 * sub + 1]);
                        mma_bf16(acc[mt][nt], al[mt], bh[2 * sub], bh[2 * sub + 1]);
                    }
            }
        }
        if (c < 3) {
            CP_WAIT0();
            __syncthreads();
        }
    }

    int g = lane >> 2, t = lane & 3;
#pragma unroll
    for (int mt = 0; mt < 4; mt++) {
        int r0 = bm + warp_m * 64 + mt * 16 + g;
#pragma unroll
        for (int nt = 0; nt < 8; nt++) {
            int col = bn + warp_n * 64 + nt * 8 + 2 * t;
            *(float2*)(C + (size_t)r0 * 32768 + col) = make_float2(acc[mt][nt][0], acc[mt][nt][1]);
            *(float2*)(C + (size_t)(r0 + 8) * 32768 + col) = make_float2(acc[mt][nt][2], acc[mt][nt][3]);
        }
    }

    if (STATS) {
        int CH = gridDim.y * 128;
#pragma unroll
        for (int mt = 0; mt < 4; mt++)
#pragma unroll
            for (int half = 0; half < 2; half++) {
                float s = 0.f, ss = 0.f;
#pragma unroll
                for (int nt = 0; nt < 8; nt++) {
                    float v0 = acc[mt][nt][half * 2], v1 = acc[mt][nt][half * 2 + 1];
                    s += v0 + v1;
                    ss = fmaf(v0, v0, ss); ss = fmaf(v1, v1, ss);
                }
                s  += __shfl_xor_sync(0xffffffffu, s, 1);
                s  += __shfl_xor_sync(0xffffffffu, s, 2);
                ss += __shfl_xor_sync(0xffffffffu, ss, 1);
                ss += __shfl_xor_sync(0xffffffffu, ss, 2);
                if (t == 0) {
                    int row = bm + warp_m * 64 + mt * 16 + half * 8 + g;
                    float* dst = part + ((size_t)(blockIdx.x * 2 + warp_n) * CH + row) * 2;
                    dst[0] = s; dst[1] = ss;
                }
            }
    }
}

// ------------------------------ misc helpers --------------------------------
__device__ __forceinline__ float warpSum(float v) {
#pragma unroll
    for (int o = 16; o > 0; o >>= 1) v += __shfl_xor_sync(0xffffffffu, v, o);
    return v;
}
__device__ __forceinline__ void blockReduce2(float& a, float& b) {
    __shared__ float sa[8], sb2[8];
    int lane = threadIdx.x & 31, w = threadIdx.x >> 5;
#pragma unroll
    for (int o = 16; o > 0; o >>= 1) {
        a += __shfl_xor_sync(0xffffffffu, a, o);
        b += __shfl_xor_sync(0xffffffffu, b, o);
    }
    if (lane == 0) { sa[w] = a; sb2[w] = b; }
    __syncthreads();
    a = (threadIdx.x < 8) ? sa[threadIdx.x] : 0.f;
    b = (threadIdx.x < 8) ? sb2[threadIdx.x] : 0.f;
    if (w == 0) {
#pragma unroll
        for (int o = 4; o > 0; o >>= 1) {
            a += __shfl_xor_sync(0xffffffffu, a, o);
            b += __shfl_xor_sync(0xffffffffu, b, o);
        }
    }
}
__device__ __forceinline__ void bn_coef(const float* sums, const float* gamma,
                                        const float* beta, int c, float invN,
                                        float& s, float& t) {
    float mean = sums[c * 2] * invN;
    float var  = sums[c * 2 + 1] * invN - mean * mean;
    s = gamma[c] * rsqrtf(var + EPSV);
    t = beta[c] - mean * s;
}
__device__ __forceinline__ void split4(float a, float b, float c, float d,
                                       uint2& hi, uint2& lo) {
    uint32_t l0, l1;
    uint32_t h0 = pack_hilo(a, b, l0);
    uint32_t h1 = pack_hilo(c, d, l1);
    hi = make_uint2(h0, h1);
    lo = make_uint2(l0, l1);
}

__global__ void __launch_bounds__(256) sumreduce_k(const float* __restrict__ part,
                                                   int P, int CH, float* __restrict__ out) {
    int ch = blockIdx.x;
    float s = 0.f, ss = 0.f;
    for (int p = threadIdx.x; p < P; p += 256) {
        const float* q = part + ((size_t)p * CH + ch) * 2;
        s += q[0]; ss += q[1];
    }
    blockReduce2(s, ss);
    if (threadIdx.x == 0) { out[ch * 2] = s; out[ch * 2 + 1] = ss; }
}

__global__ void __launch_bounds__(256) sumreduceA_k(const float* __restrict__ pA,
                                                    float* __restrict__ out) {
    int ch = blockIdx.x;
    int s_ = ch >> 7, c2 = ch & 127, h = c2 >> 4, il = c2 & 15;
    float s = 0.f, ss = 0.f;
    for (int bb = threadIdx.x; bb < 512; bb += 256) {
        const float* q = pA + (size_t)(bb * 8 + h) * 64 + il * 4 + s_ * 2;
        s += q[0]; ss += q[1];
    }
    blockReduce2(s, ss);
    if (threadIdx.x == 0) { out[ch * 2] = s; out[ch * 2 + 1] = ss; }
}

// ----- T1 --------------------------------------------------------------------
__global__ void __launch_bounds__(256) t1_k(const float* __restrict__ conv1,
                                            const float* __restrict__ sums,
                                            const float* __restrict__ gamma,
                                            const float* __restrict__ beta,
                                            __nv_bfloat16* __restrict__ xh,
                                            __nv_bfloat16* __restrict__ xl) {
    __shared__ float tile[64][65];
    int o = blockIdx.x, b = blockIdx.y;
    float s, t;
    bn_coef(sums, gamma, beta, o, 1.0f / 32768.0f, s, t);
    const float* src = conv1 + (size_t)o * 32768 + b * 4096;
    size_t dsto = (size_t)o * 32768 + b * 4096;
#pragma unroll
    for (int it = 0; it < 4; it++) {
        int f = threadIdx.x + it * 256;
        int h = f >> 4, w4 = (f & 15) * 4;
        float4 v = *(const float4*)(src + h * 64 + w4);
        tile[w4 + 0][h] = fmaxf(fmaf(v.x, s, t), 0.f);
        tile[w4 + 1][h] = fmaxf(fmaf(v.y, s, t), 0.f);
        tile[w4 + 2][h] = fmaxf(fmaf(v.z, s, t), 0.f);
        tile[w4 + 3][h] = fmaxf(fmaf(v.w, s, t), 0.f);
    }
    __syncthreads();
#pragma unroll
    for (int it = 0; it < 4; it++) {
        int f = threadIdx.x + it * 256;
        int w = f >> 4, h4 = (f & 15) * 4;
        uint2 hi, lo;
        split4(tile[w][h4], tile[w][h4 + 1], tile[w][h4 + 2], tile[w][h4 + 3], hi, lo);
        *(uint2*)(xh + dsto + w * 64 + h4) = hi;
        *(uint2*)(xl + dsto + w * 64 + h4) = lo;
    }
}

// ----- closed-form attention BN stats ----------------------------------------
__global__ void __launch_bounds__(256) att_stats_k(const float* __restrict__ qkv,
                                                   const float* __restrict__ rel,
                                                   float* __restrict__ part) {
    __shared__ float Ws[72 * 64];
    __shared__ float Ss[16 * 64];
    int bb = blockIdx.x;
    int tid = threadIdx.x;
    if (tid < 72) {
        int grp = (tid < 36) ? 0 : 1;
        int pr  = (tid < 36) ? tid : tid - 36;
        int i = 0, r = pr;
        while (r >= 8 - i) { r -= 8 - i; i++; }
        int i2 = i + r;
        const float* ra = rel + (grp * 8 + i)  * 127;
        const float* rb = rel + (grp * 8 + i2) * 127;
        float w = 0.f;
        for (int p = 0; p < 64; p++) w = fmaf(ra[p], rb[p], w);
        Ws[tid * 64 + 0] = w;
        for (int d = 1; d < 64; d++) {
            w += ra[d + 63] * rb[d + 63] - ra[d - 1] * rb[d - 1];
            Ws[tid * 64 + d] = w;
        }
    } else if (tid < 88) {
        int rr = tid - 72;
        const float* ra = rel + rr * 127;
        float s = 0.f;
        for (int p = 0; p < 64; p++) s += ra[p];
        Ss[rr * 64 + 0] = s;
        for (int d = 1; d < 64; d++) { s += ra[d + 63] - ra[d - 1]; Ss[rr * 64 + d] = s; }
    }
    __syncthreads();
    int h = tid >> 5, lane = tid & 31;
    float q[8][2], k[8][2];
#pragma unroll
    for (int i = 0; i < 8; i++) {
        const float* pq = qkv + (size_t)(i * 8 + h) * 32768 + bb * 64;
        const float* pk = qkv + (size_t)((8 + i) * 8 + h) * 32768 + bb * 64;
        q[i][0] = pq[lane]; q[i][1] = pq[lane + 32];
        k[i][0] = pk[lane]; k[i][1] = pk[lane + 32];
    }
    float s_qr = 0.f, s_kr = 0.f;
    float Qs[8], Ks[8];
#pragma unroll
    for (int i = 0; i < 8; i++) {
        s_qr = fmaf(q[i][0], Ss[i * 64 + lane], s_qr);
        s_qr = fmaf(q[i][1], Ss[i * 64 + lane + 32], s_qr);
        s_kr = fmaf(k[i][0], Ss[(8 + i) * 64 + lane], s_kr);
        s_kr = fmaf(k[i][1], Ss[(8 + i) * 64 + lane + 32], s_kr);
        Qs[i] = warpSum(q[i][0] + q[i][1]);
        Ks[i] = warpSum(k[i][0] + k[i][1]);
    }
    float s_dots = 0.f;
#pragma unroll
    for (int i = 0; i < 8; i++) s_dots = fmaf(Qs[i], Ks[i], s_dots);

    float ss_qr = 0.f, ss_kr = 0.f, ss_dots = 0.f;
    int pr = 0;
#pragma unroll
    for (int i = 0; i < 8; i++)
#pragma unroll
        for (int i2 = i; i2 < 8; i2++) {
            float coef = (i == i2) ? 1.f : 2.f;
            float pq0 = q[i][0] * q[i2][0], pq1 = q[i][1] * q[i2][1];
            float pk0 = k[i][0] * k[i2][0], pk1 = k[i][1] * k[i2][1];
            ss_qr += coef * (pq0 * Ws[pr * 64 + lane] + pq1 * Ws[pr * 64 + lane + 32]);
            ss_kr += coef * (pk0 * Ws[(36 + pr) * 64 + lane] + pk1 * Ws[(36 + pr) * 64 + lane + 32]);
            float gq = warpSum(pq0 + pq1);
            float gk = warpSum(pk0 + pk1);
            ss_dots = fmaf(coef * gq, gk, ss_dots);
            pr++;
        }
    s_qr = warpSum(s_qr); ss_qr = warpSum(ss_qr);
    s_kr = warpSum(s_kr); ss_kr = warpSum(ss_kr);
    if (lane == 0) {
        int base = bb * 24 + h * 3;
        part[(base + 0) * 2] = s_qr;   part[(base + 0) * 2 + 1] = ss_qr;
        part[(base + 1) * 2] = s_kr;   part[(base + 1) * 2 + 1] = ss_kr;
        part[(base + 2) * 2] = s_dots; part[(base + 2) * 2 + 1] = ss_dots;
    }
}

__global__ void __launch_bounds__(256) attA_fin_k(const float* __restrict__ part,
                                                  const float* __restrict__ ga,
                                                  const float* __restrict__ ba,
                                                  float* __restrict__ scA,
                                                  float* __restrict__ shA) {
    int ch = blockIdx.x;
    float s = 0.f, ss = 0.f;
    for (int bb = threadIdx.x; bb < 512; bb += 256) {
        s  += part[(bb * 24 + ch) * 2];
        ss += part[(bb * 24 + ch) * 2 + 1];
    }
    blockReduce2(s, ss);
    if (threadIdx.x == 0) {
        const float invN = 1.0f / 2097152.0f;
        float mean = s * invN;
        float var  = ss * invN - mean * mean;
        float sc = ga[ch] * rsqrtf(var + EPSV);
        scA[ch] = sc;
        shA[ch] = ba[ch] - mean * sc;
    }
}

// ----- attention mainloop (FFMA2-packed) --------------------------------------
__global__ void __launch_bounds__(256) att_main_k(const float* __restrict__ qkv,
                                                  const float* __restrict__ rel,
                                                  const float* __restrict__ scA,
                                                  const float* __restrict__ shA,
                                                  float* __restrict__ outb,
                                                  float* __restrict__ partA) {
    int bb = blockIdx.x >> 3, h = blockIdx.x & 7;
    __shared__ float qs[8][64], ks[8][64], vs[16][68];
    __shared__ float rqs[8][128], rks[8][128], rvs[16][132];
    __shared__ float attn[64][68];
    __shared__ float stg[16][64];
    int tid = threadIdx.x;
    float sc0 = scA[h * 3 + 0], sh0 = shA[h * 3 + 0];
    float sc1 = scA[h * 3 + 1], sh1 = shA[h * 3 + 1];
    float sc2 = scA[h * 3 + 2], sh2 = shA[h * 3 + 2];

    for (int e = tid; e < 2048; e += 256) {
        int r = e >> 6, d = e & 63;
        float v = qkv[(r * 8 + h) * 32768 + bb * 64 + d];
        if (r < 8) qs[r][d] = v;
        else if (r < 16) ks[r - 8][d] = v;
        else vs[r - 16][d] = v;
    }
    for (int e = tid; e < 32 * 127; e += 256) {
        int r = e / 127, p = e % 127;
        float v = rel[e];
        if (r < 8) rqs[r][p] = v * sc0;
        else if (r < 16) rks[r - 8][p] = v * sc1;
        else rvs[r - 16][p] = v;
    }
    if (tid < 16) {
        rvs[tid][127] = 0.f;
        if (tid < 8) { rqs[tid][127] = 0.f; rks[tid][127] = 0.f; }
    }
    __syncthreads();

    // ---- logits: pairs over dd (FFMA2) + register softmax ----
    {
        int d0 = (tid >> 4) << 2;
        int j0 = (tid & 15) << 2;
        int pb = d0 - j0 + 60;
        float shsum = sh0 + sh1 + sh2;
        float2 accp[2][4];
#pragma unroll
        for (int p = 0; p < 2; p++)
#pragma unroll
            for (int jj = 0; jj < 4; jj++) accp[p][jj] = make_float2(shsum, shsum);
#pragma unroll
        for (int i = 0; i < 8; i++) {
            float4 qv = *(const float4*)&qs[i][d0];
            float4 kv = *(const float4*)&ks[i][d0];
            float4 kj = *(const float4*)&ks[i][j0];
            float r8q[8], r8k[8];
            *(float4*)&r8q[0] = *(const float4*)&rqs[i][pb];
            *(float4*)&r8q[4] = *(const float4*)&rqs[i][pb + 4];
            *(float4*)&r8k[0] = *(const float4*)&rks[i][pb];
            *(float4*)&r8k[4] = *(const float4*)&rks[i][pb + 4];
            float2 qa2[2] = {make_float2(qv.x, qv.y), make_float2(qv.z, qv.w)};
            float2 ka2[2] = {make_float2(kv.x, kv.y), make_float2(kv.z, kv.w)};
            float2 q22[2] = {make_float2(qv.x * sc2, qv.y * sc2),
                             make_float2(qv.z * sc2, qv.w * sc2)};
            float kja[4] = {kj.x, kj.y, kj.z, kj.w};
#pragma unroll
            for (int p = 0; p < 2; p++)
#pragma unroll
                for (int jj = 0; jj < 4; jj++) {
                    int base = 3 + 2 * p - jj;
                    ffma2(accp[p][jj], qa2[p], make_float2(r8q[base], r8q[base + 1]));
                    ffma2(accp[p][jj], ka2[p], make_float2(r8k[base], r8k[base + 1]));
                    ffma2(accp[p][jj], q22[p], make_float2(kja[jj], kja[jj]));
                }
        }
#pragma unroll
        for (int dd = 0; dd < 4; dd++) {
            int p = dd >> 1;
            float a0 = (dd & 1) ? accp[p][0].y : accp[p][0].x;
            float a1 = (dd & 1) ? accp[p][1].y : accp[p][1].x;
            float a2 = (dd & 1) ? accp[p][2].y : accp[p][2].x;
            float a3 = (dd & 1) ? accp[p][3].y : accp[p][3].x;
            float m = fmaxf(fmaxf(a0, a1), fmaxf(a2, a3));
#pragma unroll
            for (int o = 8; o > 0; o >>= 1) m = fmaxf(m, __shfl_xor_sync(0xffffffffu, m, o));
            float e0 = __expf(a0 - m), e1 = __expf(a1 - m);
            float e2 = __expf(a2 - m), e3 = __expf(a3 - m);
            float s = e0 + e1 + e2 + e3;
#pragma unroll
            for (int o = 8; o > 0; o >>= 1) s += __shfl_xor_sync(0xffffffffu, s, o);
            float inv = 1.f / s;
            *(float4*)&attn[d0 + dd][j0] = make_float4(e0 * inv, e1 * inv, e2 * inv, e3 * inv);
        }
    }
    __syncthreads();

    // ---- sv & sve: pairs over dd (FFMA2), conflict-free j mapping ----
    {
        int dg = tid >> 4;
        int ig = (tid >> 2) & 3;
        int jq = tid & 3;
        int d0 = dg << 2, i0 = ig << 2;
        float2 asv2[4][2], asve2[4][2];
#pragma unroll
        for (int a = 0; a < 4; a++)
#pragma unroll
            for (int p = 0; p < 2; p++) {
                asv2[a][p] = make_float2(0.f, 0.f);
                asve2[a][p] = make_float2(0.f, 0.f);
            }

#pragma unroll
        for (int itblk = 0; itblk < 4; itblk++) {
            int j4 = itblk * 16 + jq * 4;
            float a[4][4];
#pragma unroll
            for (int dd = 0; dd < 4; dd++)
                *(float4*)a[dd] = *(const float4*)&attn[d0 + dd][j4];
            float2 ap[2][4];
#pragma unroll
            for (int p = 0; p < 2; p++)
#pragma unroll
                for (int jj = 0; jj < 4; jj++)
                    ap[p][jj] = make_float2(a[2 * p][jj], a[2 * p + 1][jj]);
            int pb = d0 - j4 + 60;
#pragma unroll
            for (int ii = 0; ii < 4; ii++) {
                int i = i0 + ii;
                float vv[4];
                *(float4*)vv = *(const float4*)&vs[i][j4];
                float r8[8];
                *(float4*)&r8[0] = *(const float4*)&rvs[i][pb];
                *(float4*)&r8[4] = *(const float4*)&rvs[i][pb + 4];
#pragma unroll
                for (int p = 0; p < 2; p++)
#pragma unroll
                    for (int jj = 0; jj < 4; jj++) {
                        ffma2(asv2[ii][p], ap[p][jj], make_float2(vv[jj], vv[jj]));
                        int base = 3 + 2 * p - jj;
                        ffma2(asve2[ii][p], ap[p][jj], make_float2(r8[base], r8[base + 1]));
                    }
            }
        }
        float asv[4][4], asve[4][4];
#pragma unroll
        for (int ii = 0; ii < 4; ii++)
#pragma unroll
            for (int p = 0; p < 2; p++) {
                asv[ii][2 * p] = asv2[ii][p].x;  asv[ii][2 * p + 1] = asv2[ii][p].y;
                asve[ii][2 * p] = asve2[ii][p].x; asve[ii][2 * p + 1] = asve2[ii][p].y;
            }
#pragma unroll
        for (int ii = 0; ii < 4; ii++)
#pragma unroll
            for (int dd = 0; dd < 4; dd++) {
                asv[ii][dd]  += __shfl_xor_sync(0xffffffffu, asv[ii][dd], 1);
                asv[ii][dd]  += __shfl_xor_sync(0xffffffffu, asv[ii][dd], 2);
                asve[ii][dd] += __shfl_xor_sync(0xffffffffu, asve[ii][dd], 1);
                asve[ii][dd] += __shfl_xor_sync(0xffffffffu, asve[ii][dd], 2);
            }
        if (jq == 0) {
#pragma unroll
            for (int ii = 0; ii < 4; ii++) {
                int c2 = h * 16 + i0 + ii;
                size_t o0 = ((size_t)bb * 128 + c2) * 64 + d0;
                *(float4*)&outb[o0] = make_float4(asve[ii][0], asve[ii][1], asve[ii][2], asve[ii][3]);
                *(float4*)&outb[o0 + (size_t)512 * 128 * 64] =
                    make_float4(asv[ii][0], asv[ii][1], asv[ii][2], asv[ii][3]);
                float se = 0.f, qe = 0.f, sv_ = 0.f, qv_ = 0.f;
#pragma unroll
                for (int dd = 0; dd < 4; dd++) {
                    se += asve[ii][dd]; qe = fmaf(asve[ii][dd], asve[ii][dd], qe);
                    sv_ += asv[ii][dd]; qv_ = fmaf(asv[ii][dd], asv[ii][dd], qv_);
                }
                *(float4*)&stg[dg][(i0 + ii) * 4] = make_float4(se, qe, sv_, qv_);
            }
        }
    }
    __syncthreads();
    if (tid < 64) {
        float acc = 0.f;
#pragma unroll
        for (int dg = 0; dg < 16; dg++) acc += stg[dg][tid];
        partA[(size_t)blockIdx.x * 64 + tid] = acc;
    }
}

// ----- T2 --------------------------------------------------------------------
__global__ void __launch_bounds__(256) t2_k(const float* __restrict__ outb,
                                            const float* __restrict__ sums,
                                            const float* __restrict__ gamma,
                                            const float* __restrict__ beta,
                                            __nv_bfloat16* __restrict__ xh,
                                            __nv_bfloat16* __restrict__ xl) {
    __shared__ float tile[64][65];
    int c2 = blockIdx.x, b = blockIdx.y;
    float s0, h0, s1, h1;
    bn_coef(sums, gamma, beta, c2,       1.0f / 32768.0f, s0, h0);
    bn_coef(sums, gamma, beta, 128 + c2, 1.0f / 32768.0f, s1, h1);
    const float* base0 = outb + ((size_t)(b * 64) * 128 + c2) * 64;
    const float* base1 = base0 + (size_t)512 * 128 * 64;
#pragma unroll
    for (int it = 0; it < 4; it++) {
        int f = threadIdx.x + it * 256;
        int w = f >> 4, h4 = (f & 15) * 4;
        float4 v0 = *(const float4*)(base0 + w * 8192 + h4);
        float4 v1 = *(const float4*)(base1 + w * 8192 + h4);
        tile[h4 + 0][w] = fmaf(v0.x, s0, h0) + fmaf(v1.x, s1, h1);
        tile[h4 + 1][w] = fmaf(v0.y, s0, h0) + fmaf(v1.y, s1, h1);
        tile[h4 + 2][w] = fmaf(v0.z, s0, h0) + fmaf(v1.z, s1, h1);
        tile[h4 + 3][w] = fmaf(v0.w, s0, h0) + fmaf(v1.w, s1, h1);
    }
    __syncthreads();
    size_t dsto = (size_t)c2 * 32768 + b * 4096;
#pragma unroll
    for (int it = 0; it < 4; it++) {
        int f = threadIdx.x + it * 256;
        int h = f >> 4, w4 = (f & 15) * 4;
        uint2 hi, lo;
        split4(tile[h][w4], tile[h][w4 + 1], tile[h][w4 + 2], tile[h][w4 + 3], hi, lo);
        *(uint2*)(xh + dsto + h * 64 + w4) = hi;
        *(uint2*)(xl + dsto + h * 64 + w4) = lo;
    }
}

// ----- T3 --------------------------------------------------------------------
__global__ void __launch_bounds__(256) t3_k(const float* __restrict__ outb,
                                            const float* __restrict__ sums,
                                            const float* __restrict__ gamma,
                                            const float* __restrict__ beta,
                                            __nv_bfloat16* __restrict__ xh,
                                            __nv_bfloat16* __restrict__ xl) {
    int g = (blockIdx.x * 256 + threadIdx.x) * 4;
    int w  = g & 63;
    int r  = g >> 6;
    int h  = r & 63;
    int c2 = (r >> 6) & 127;
    int b  = r >> 13;
    int bb = b * 64 + h;
    float s0, h0, s1, h1;
    bn_coef(sums, gamma, beta, c2,       1.0f / 32768.0f, s0, h0);
    bn_coef(sums, gamma, beta, 128 + c2, 1.0f / 32768.0f, s1, h1);
    float4 v0 = *(const float4*)(outb + ((size_t)bb * 128 + c2) * 64 + w);
    float4 v1 = *(const float4*)(outb + ((size_t)(512 + bb) * 128 + c2) * 64 + w);
    float o0 = fmaxf(fmaf(v0.x, s0, h0) + fmaf(v1.x, s1, h1), 0.f);
    float o1 = fmaxf(fmaf(v0.y, s0, h0) + fmaf(v1.y, s1, h1), 0.f);
    float o2 = fmaxf(fmaf(v0.z, s0, h0) + fmaf(v1.z, s1, h1), 0.f);
    float o3 = fmaxf(fmaf(v0.w, s0, h0) + fmaf(v1.w, s1, h1), 0.f);
    uint2 hi, lo;
    split4(o0, o1, o2, o3, hi, lo);
    *(uint2*)(xh + g) = hi;
    *(uint2*)(xl + g) = lo;
}

// ----- final -------------------------------------------------------------------
__global__ void __launch_bounds__(256) final_k(const float* __restrict__ co,
                                               const float* __restrict__ sums,
                                               const float* __restrict__ gamma,
                                               const float* __restrict__ beta,
                                               const float* __restrict__ x_in,
                                               float* __restrict__ out) {
    int g = (blockIdx.x * 256 + threadIdx.x) * 4;
    int o  = (g >> 12) & 255;
    int b  = g >> 20;
    int hw = g & 4095;
    float s, t;
    bn_coef(sums, gamma, beta, o, 1.0f / 32768.0f, s, t);
    float4 c = *(const float4*)(co + (size_t)o * 32768 + b * 4096 + hw);
    float4 x = *(const float4*)(x_in + g);
    float4 y;
    y.x = fmaxf(fmaf(c.x, s, t) + x.x, 0.f);
    y.y = fmaxf(fmaf(c.y, s, t) + x.y, 0.f);
    y.z = fmaxf(fmaf(c.z, s, t) + x.z, 0.f);
    y.w = fmaxf(fmaf(c.w, s, t) + x.w, 0.f);
    *(float4*)(out + g) = y;
}

// ---------------------------------------------------------------------------
extern "C" void kernel_launch(void* const* d_in, const int* in_sizes, int n_in,
                              void* d_out, int out_size) {
    const float* x_in   = (const float*)d_in[0];
    const float* w_in   = (const float*)d_in[1];
    const float* g_in   = (const float*)d_in[2];
    const float* b_in   = (const float*)d_in[3];
    const float* w_out  = (const float*)d_in[4];
    const float* gout   = (const float*)d_in[5];
    const float* bout   = (const float*)d_in[6];
    const float* wqkv_h = (const float*)d_in[7];
    const float* rel_h  = (const float*)d_in[8];
    const float* ga_h   = (const float*)d_in[9];
    const float* ba_h   = (const float*)d_in[10];
    const float* go_h   = (const float*)d_in[11];
    const float* bo_h   = (const float*)d_in[12];
    const float* wqkv_w = (const float*)d_in[13];
    const float* rel_w  = (const float*)d_in[14];
    const float* ga_w   = (const float*)d_in[15];
    const float* ba_w   = (const float*)d_in[16];
    const float* go_w   = (const float*)d_in[17];
    const float* bo_w   = (const float*)d_in[18];
    float* out = (float*)d_out;

    float *conv1, *qkv, *outb, *co, *part, *partG, *partA, *sum, *scA, *shA;
    __nv_bfloat16 *x1h, *x1l, *x2h, *x2l, *x3h, *x3l;
    cudaGetSymbolAddress((void**)&conv1, g_conv1);
    cudaGetSymbolAddress((void**)&qkv,   g_qkv);
    cudaGetSymbolAddress((void**)&outb,  g_outb);
    cudaGetSymbolAddress((void**)&co,    g_co);
    cudaGetSymbolAddress((void**)&part,  g_part);
    cudaGetSymbolAddress((void**)&partG, g_partG);
    cudaGetSymbolAddress((void**)&partA, g_partA);
    cudaGetSymbolAddress((void**)&sum,   g_sum);
    cudaGetSymbolAddress((void**)&scA,   g_scA);
    cudaGetSymbolAddress((void**)&shA,   g_shA);
    cudaGetSymbolAddress((void**)&x1h,   g_x1h);
    cudaGetSymbolAddress((void**)&x1l,   g_x1l);
    cudaGetSymbolAddress((void**)&x2h,   g_x2h);
    cudaGetSymbolAddress((void**)&x2l,   g_x2l);
    cudaGetSymbolAddress((void**)&x3h,   g_x3h);
    cudaGetSymbolAddress((void**)&x3l,   g_x3l);

    const int SMEM_OLD = 71680;
    const int SMEM_CA  = 104448;   // 2x A(34816) + 2x Bstage(17408)
    cudaFuncSetAttribute((const void*)gemm_mma<256, 1, true>, cudaFuncAttributeMaxDynamicSharedMemorySize, SMEM_OLD);
    cudaFuncSetAttribute((const void*)gemm_ca<0, false>,      cudaFuncAttributeMaxDynamicSharedMemorySize, SMEM_CA);
    cudaFuncSetAttribute((const void*)gemm_ca<1, true>,       cudaFuncAttributeMaxDynamicSharedMemorySize, SMEM_CA);

    // conv_in (fp32 path, fused BN stats)
    gemm_mma<256, 1, true><<<dim3(256, 1), 128, SMEM_OLD>>>(w_in, x_in, conv1, partG);
    sumreduce_k<<<128, 256>>>(partG, 512, 128, sum);
    t1_k<<<dim3(128, 8), 256>>>(conv1, sum, g_in, b_in, x1h, x1l);

    // axial attention along H
    gemm_ca<0, false><<<dim3(256, 2), 128, SMEM_CA>>>(wqkv_h, x1h, x1l, qkv, nullptr);
    att_stats_k<<<512, 256>>>(qkv, rel_h, part);
    attA_fin_k<<<24, 256>>>(part, ga_h, ba_h, scA, shA);
    att_main_k<<<4096, 256>>>(qkv, rel_h, scA, shA, outb, partA);
    sumreduceA_k<<<256, 256>>>(partA, sum);
    t2_k<<<dim3(128, 8), 256>>>(outb, sum, go_h, bo_h, x2h, x2l);

    // axial attention along W
    gemm_ca<0, false><<<dim3(256, 2), 128, SMEM_CA>>>(wqkv_w, x2h, x2l, qkv, nullptr);
    att_stats_k<<<512, 256>>>(qkv, rel_w, part);
    attA_fin_k<<<24, 256>>>(part, ga_w, ba_w, scA, shA);
    att_main_k<<<4096, 256>>>(qkv, rel_w, scA, shA, outb, partA);
    sumreduceA_k<<<256, 256>>>(partA, sum);
    t3_k<<<4096, 256>>>(outb, sum, go_w, bo_w, x3h, x3l);

    // conv_out (fused BN stats) + residual + relu
    gemm_ca<1, true><<<dim3(256, 2), 128, SMEM_CA>>>(w_out, x3h, x3l, co, partG);
    sumreduce_k<<<256, 256>>>(partG, 512, 256, sum);
    final_k<<<8192, 256>>>(co, sum, gout, bout, x_in, out);
}

// round 13
// speedup vs baseline: 1.0238x; 1.0238x over previous
#include <cuda_runtime.h>
#include <cuda_bf16.h>
#include <cstdint>

#define EPSV 1e-5f

// ------------------------- scratch (global, static) ------------------------
__device__ float g_conv1[128 * 32768];
__device__ float g_qkv [256 * 32768];
__device__ float g_outb[2 * 512 * 128 * 64];
__device__ float g_co  [256 * 32768];
__device__ float g_part[512 * 24 * 2];
__device__ float g_partG[512 * 256 * 2];
__device__ float g_partA[4096 * 64];
__device__ float g_sum [512];
__device__ float g_scA [24];
__device__ float g_shA [24];
__device__ __nv_bfloat16 g_x1h[128 * 32768], g_x1l[128 * 32768];
__device__ __nv_bfloat16 g_x2h[128 * 32768], g_x2l[128 * 32768];
__device__ __nv_bfloat16 g_x3h[128 * 32768], g_x3l[128 * 32768];

// ========================= helpers ==========================================
__device__ __forceinline__ uint32_t smem_u32(const void* p) {
    uint32_t a;
    asm("{ .reg .u64 t; cvta.to.shared.u64 t, %1; cvt.u32.u64 %0, t; }" : "=r"(a) : "l"(p));
    return a;
}
__device__ __forceinline__ void ldsm_x4(uint32_t (&r)[4], uint32_t addr) {
    asm volatile("ldmatrix.sync.aligned.m8n8.x4.shared.b16 {%0,%1,%2,%3}, [%4];"
                 : "=r"(r[0]), "=r"(r[1]), "=r"(r[2]), "=r"(r[3]) : "r"(addr));
}
__device__ __forceinline__ void ldsm_x4t(uint32_t (&r)[4], uint32_t addr) {
    asm volatile("ldmatrix.sync.aligned.m8n8.x4.trans.shared.b16 {%0,%1,%2,%3}, [%4];"
                 : "=r"(r[0]), "=r"(r[1]), "=r"(r[2]), "=r"(r[3]) : "r"(addr));
}
__device__ __forceinline__ void mma_bf16(float (&c)[4], const uint32_t (&a)[4],
                                         uint32_t b0, uint32_t b1) {
    asm volatile("mma.sync.aligned.m16n8k16.row.col.f32.bf16.bf16.f32 "
                 "{%0,%1,%2,%3}, {%4,%5,%6,%7}, {%8,%9}, {%0,%1,%2,%3};"
                 : "+f"(c[0]), "+f"(c[1]), "+f"(c[2]), "+f"(c[3])
                 : "r"(a[0]), "r"(a[1]), "r"(a[2]), "r"(a[3]), "r"(b0), "r"(b1));
}
__device__ __forceinline__ uint32_t pack_hilo(float x, float y, uint32_t& lo) {
    __nv_bfloat162 h = __floats2bfloat162_rn(x, y);
    float rx = x - __bfloat162float(h.x);
    float ry = y - __bfloat162float(h.y);
    __nv_bfloat162 l = __floats2bfloat162_rn(rx, ry);
    lo = *reinterpret_cast<uint32_t*>(&l);
    return *reinterpret_cast<uint32_t*>(&h);
}
__device__ __forceinline__ void cp16(uint32_t smem_addr, const void* gptr) {
    asm volatile("cp.async.cg.shared.global [%0], [%1], 16;"
                 :: "r"(smem_addr), "l"(gptr) : "memory");
}
#define CP_COMMIT() asm volatile("cp.async.commit_group;" ::: "memory")
#define CP_WAIT0()  asm volatile("cp.async.wait_group 0;" ::: "memory")

// ============== GEMM A (fp32 operands, in-kernel split) — conv_in ===========
template <int KDIM, int MODE, bool STATS>
__global__ void __launch_bounds__(128) gemm_mma(const float* __restrict__ A,
                                                const float* __restrict__ Bm,
                                                float* __restrict__ C,
                                                float* __restrict__ part) {
    constexpr uint32_t AL_B = 128 * 72 * 2;
    constexpr uint32_t BH_B = 2 * AL_B;
    constexpr uint32_t BL_B = BH_B + 64 * 136 * 2;

    extern __shared__ __align__(16) char smem[];
    __nv_bfloat16* sAh = (__nv_bfloat16*)smem;
    __nv_bfloat16* sAl = (__nv_bfloat16*)(smem + AL_B);
    __nv_bfloat16* sBh = (__nv_bfloat16*)(smem + BH_B);
    __nv_bfloat16* sBl = (__nv_bfloat16*)(smem + BL_B);
    uint32_t sbase = smem_u32(smem);

    int tid = threadIdx.x, lane = tid & 31, wid = tid >> 5;
    int warp_m = wid & 1, warp_n = wid >> 1;
    int bn = blockIdx.x * 128;
    int bm = blockIdx.y * 128;

    int a_row_off = ((lane >> 3) & 1) * 8 + (lane & 7);
    int a_k_off   = (lane >> 4) * 8;
    int b_k_off   = a_row_off;
    int b_n_off   = a_k_off;

    float acc[4][8][4];
#pragma unroll
    for (int mt = 0; mt < 4; mt++)
#pragma unroll
        for (int nt = 0; nt < 8; nt++)
#pragma unroll
            for (int r = 0; r < 4; r++) acc[mt][nt][r] = 0.f;

    for (int k0 = 0; k0 < KDIM; k0 += 64) {
#pragma unroll
        for (int it = 0; it < 16; it++) {
            int flat = it * 128 + tid;
            int row = flat >> 4, c4 = (flat & 15) << 2;
            float4 v = *(const float4*)(A + (size_t)(bm + row) * KDIM + k0 + c4);
            uint32_t l0, l1;
            uint32_t h0 = pack_hilo(v.x, v.y, l0);
            uint32_t h1 = pack_hilo(v.z, v.w, l1);
            uint32_t off = (uint32_t)(row * 72 + c4);
            *(uint2*)(sAh + off) = make_uint2(h0, h1);
            *(uint2*)(sAl + off) = make_uint2(l0, l1);
        }
#pragma unroll
        for (int it = 0; it < 16; it++) {
            int flat = it * 128 + tid;
            int row = flat >> 5, c4 = (flat & 31) << 2;
            const float* br = (MODE == 0)
                ? Bm + (size_t)(k0 + row) * 32768 + bn + c4
                : Bm + ((size_t)(bn >> 12) * KDIM + k0 + row) * 4096 + (bn & 4095) + c4;
            float4 v = *(const float4*)br;
            uint32_t l0, l1;
            uint32_t h0 = pack_hilo(v.x, v.y, l0);
            uint32_t h1 = pack_hilo(v.z, v.w, l1);
            uint32_t off = (uint32_t)(row * 136 + c4);
            *(uint2*)(sBh + off) = make_uint2(h0, h1);
            *(uint2*)(sBl + off) = make_uint2(l0, l1);
        }
        __syncthreads();

#pragma unroll
        for (int ks = 0; ks < 4; ks++) {
            uint32_t ah[4][4], al[4][4];
#pragma unroll
            for (int mt = 0; mt < 4; mt++) {
                uint32_t addr = sbase +
                    (uint32_t)(((warp_m * 64 + mt * 16 + a_row_off) * 72 + ks * 16 + a_k_off) * 2);
                ldsm_x4(ah[mt], addr);
                ldsm_x4(al[mt], addr + AL_B);
            }
#pragma unroll
            for (int gi = 0; gi < 4; gi++) {
                uint32_t bh[4], bl[4];
                uint32_t addr = sbase + BH_B +
                    (uint32_t)(((ks * 16 + b_k_off) * 136 + warp_n * 64 + gi * 16 + b_n_off) * 2);
                ldsm_x4t(bh, addr);
                ldsm_x4t(bl, addr + (BL_B - BH_B));
#pragma unroll
                for (int mt = 0; mt < 4; mt++)
#pragma unroll
                    for (int sub = 0; sub < 2; sub++) {
                        int nt = gi * 2 + sub;
                        mma_bf16(acc[mt][nt], ah[mt], bh[2 * sub], bh[2 * sub + 1]);
                        mma_bf16(acc[mt][nt], ah[mt], bl[2 * sub], bl[2 * sub + 1]);
                        mma_bf16(acc[mt][nt], al[mt], bh[2 * sub], bh[2 * sub + 1]);
                    }
            }
        }
        __syncthreads();
    }

    int g = lane >> 2, t = lane & 3;
#pragma unroll
    for (int mt = 0; mt < 4; mt++) {
        int r0 = bm + warp_m * 64 + mt * 16 + g;
#pragma unroll
        for (int nt = 0; nt < 8; nt++) {
            int col = bn + warp_n * 64 + nt * 8 + 2 * t;
            *(float2*)(C + (size_t)r0 * 32768 + col) = make_float2(acc[mt][nt][0], acc[mt][nt][1]);
            *(float2*)(C + (size_t)(r0 + 8) * 32768 + col) = make_float2(acc[mt][nt][2], acc[mt][nt][3]);
        }
    }

    if (STATS) {
        int CH = gridDim.y * 128;
#pragma unroll
        for (int mt = 0; mt < 4; mt++)
#pragma unroll
            for (int half = 0; half < 2; half++) {
                float s = 0.f, ss = 0.f;
#pragma unroll
                for (int nt = 0; nt < 8; nt++) {
                    float v0 = acc[mt][nt][half * 2], v1 = acc[mt][nt][half * 2 + 1];
                    s += v0 + v1;
                    ss = fmaf(v0, v0, ss); ss = fmaf(v1, v1, ss);
                }
                s  += __shfl_xor_sync(0xffffffffu, s, 1);
                s  += __shfl_xor_sync(0xffffffffu, s, 2);
                ss += __shfl_xor_sync(0xffffffffu, ss, 1);
                ss += __shfl_xor_sync(0xffffffffu, ss, 2);
                if (t == 0) {
                    int row = bm + warp_m * 64 + mt * 16 + half * 8 + g;
                    float* dst = part + ((size_t)(blockIdx.x * 2 + warp_n) * CH + row) * 2;
                    dst[0] = s; dst[1] = ss;
                }
            }
    }
}

// ===== GEMM B: A fp32 weights split in prologue (full-K resident), B bf16 ===
template <int MODE, bool STATS>
__global__ void __launch_bounds__(128) gemm_ca(const float* __restrict__ A,
                                               const __nv_bfloat16* __restrict__ Bhg,
                                               const __nv_bfloat16* __restrict__ Blg,
                                               float* __restrict__ C,
                                               float* __restrict__ part) {
    constexpr int KDIM = 128;
    constexpr uint32_t A_SZ   = 128 * 136 * 2;
    constexpr uint32_t B_SZ   = 32 * 136 * 2;
    constexpr uint32_t BSTAGE = 2 * B_SZ;
    constexpr uint32_t B_OFF  = 2 * A_SZ;

    extern __shared__ __align__(16) char smem[];
    __nv_bfloat16* sAh = (__nv_bfloat16*)smem;
    __nv_bfloat16* sAl = (__nv_bfloat16*)(smem + A_SZ);
    uint32_t sbase = smem_u32(smem);

    int tid = threadIdx.x, lane = tid & 31, wid = tid >> 5;
    int warp_m = wid & 1, warp_n = wid >> 1;
    int bn = blockIdx.x * 128;
    int bm = blockIdx.y * 128;

    int a_row_off = ((lane >> 3) & 1) * 8 + (lane & 7);
    int a_k_off   = (lane >> 4) * 8;
    int b_k_off   = a_row_off;
    int b_n_off   = a_k_off;

    float acc[4][8][4];
#pragma unroll
    for (int mt = 0; mt < 4; mt++)
#pragma unroll
        for (int nt = 0; nt < 8; nt++)
#pragma unroll
            for (int r = 0; r < 4; r++) acc[mt][nt][r] = 0.f;

    auto issue = [&](int c) {
        uint32_t st = sbase + B_OFF + (uint32_t)(c & 1) * BSTAGE;
        int k0 = c * 32;
#pragma unroll
        for (int it = 0; it < 4; it++) {
            int flat = it * 128 + tid;
            int row = flat >> 4, seg = (flat & 15) * 8;
            size_t goff = (MODE == 0)
                ? (size_t)(k0 + row) * 32768 + bn + seg
                : ((size_t)(bn >> 12) * KDIM + k0 + row) * 4096 + (bn & 4095) + seg;
            uint32_t soff = (uint32_t)(row * 136 + seg) * 2;
            cp16(st + soff, Bhg + goff);
            cp16(st + B_SZ + soff, Blg + goff);
        }
        CP_COMMIT();
    };

    issue(0);
#pragma unroll
    for (int it = 0; it < 32; it++) {
        int flat = it * 128 + tid;
        int row = flat >> 5, c4 = (flat & 31) << 2;
        float4 v = *(const float4*)(A + (size_t)(bm + row) * KDIM + c4);
        uint32_t l0, l1;
        uint32_t h0 = pack_hilo(v.x, v.y, l0);
        uint32_t h1 = pack_hilo(v.z, v.w, l1);
        uint32_t off = (uint32_t)(row * 136 + c4);
        *(uint2*)(sAh + off) = make_uint2(h0, h1);
        *(uint2*)(sAl + off) = make_uint2(l0, l1);
    }
    CP_WAIT0();
    __syncthreads();

#pragma unroll
    for (int c = 0; c < 4; c++) {
        if (c < 3) issue(c + 1);
        uint32_t stB = sbase + B_OFF + (uint32_t)(c & 1) * BSTAGE;
#pragma unroll
        for (int ks = 0; ks < 2; ks++) {
            uint32_t ah[4][4], al[4][4];
#pragma unroll
            for (int mt = 0; mt < 4; mt++) {
                uint32_t addr = sbase +
                    (uint32_t)(((warp_m * 64 + mt * 16 + a_row_off) * 136 + c * 32 + ks * 16 + a_k_off) * 2);
                ldsm_x4(ah[mt], addr);
                ldsm_x4(al[mt], addr + A_SZ);
            }
#pragma unroll
            for (int gi = 0; gi < 4; gi++) {
                uint32_t bh[4], bl[4];
                uint32_t addr = stB +
                    (uint32_t)(((ks * 16 + b_k_off) * 136 + warp_n * 64 + gi * 16 + b_n_off) * 2);
                ldsm_x4t(bh, addr);
                ldsm_x4t(bl, addr + B_SZ);
#pragma unroll
                for (int mt = 0; mt < 4; mt++)
#pragma unroll
                    for (int sub = 0; sub < 2; sub++) {
                        int nt = gi * 2 + sub;
                        mma_bf16(acc[mt][nt], ah[mt], bh[2 * sub], bh[2 * sub + 1]);
                        mma_bf16(acc[mt][nt], ah[mt], bl[2 * sub], bl[2 * sub + 1]);
                        mma_bf16(acc[mt][nt], al[mt], bh[2 * sub], bh[2 * sub + 1]);
                    }
            }
        }
        if (c < 3) {
            CP_WAIT0();
            __syncthreads();
        }
    }

    int g = lane >> 2, t = lane & 3;
#pragma unroll
    for (int mt = 0; mt < 4; mt++) {
        int r0 = bm + warp_m * 64 + mt * 16 + g;
#pragma unroll
        for (int nt = 0; nt < 8; nt++) {
            int col = bn + warp_n * 64 + nt * 8 + 2 * t;
            *(float2*)(C + (size_t)r0 * 32768 + col) = make_float2(acc[mt][nt][0], acc[mt][nt][1]);
            *(float2*)(C + (size_t)(r0 + 8) * 32768 + col) = make_float2(acc[mt][nt][2], acc[mt][nt][3]);
        }
    }

    if (STATS) {
        int CH = gridDim.y * 128;
#pragma unroll
        for (int mt = 0; mt < 4; mt++)
#pragma unroll
            for (int half = 0; half < 2; half++) {
                float s = 0.f, ss = 0.f;
#pragma unroll
                for (int nt = 0; nt < 8; nt++) {
                    float v0 = acc[mt][nt][half * 2], v1 = acc[mt][nt][half * 2 + 1];
                    s += v0 + v1;
                    ss = fmaf(v0, v0, ss); ss = fmaf(v1, v1, ss);
                }
                s  += __shfl_xor_sync(0xffffffffu, s, 1);
                s  += __shfl_xor_sync(0xffffffffu, s, 2);
                ss += __shfl_xor_sync(0xffffffffu, ss, 1);
                ss += __shfl_xor_sync(0xffffffffu, ss, 2);
                if (t == 0) {
                    int row = bm + warp_m * 64 + mt * 16 + half * 8 + g;
                    float* dst = part + ((size_t)(blockIdx.x * 2 + warp_n) * CH + row) * 2;
                    dst[0] = s; dst[1] = ss;
                }
            }
    }
}

// ------------------------------ misc helpers --------------------------------
__device__ __forceinline__ float warpSum(float v) {
#pragma unroll
    for (int o = 16; o > 0; o >>= 1) v += __shfl_xor_sync(0xffffffffu, v, o);
    return v;
}
__device__ __forceinline__ void blockReduce2(float& a, float& b) {
    __shared__ float sa[8], sb2[8];
    int lane = threadIdx.x & 31, w = threadIdx.x >> 5;
#pragma unroll
    for (int o = 16; o > 0; o >>= 1) {
        a += __shfl_xor_sync(0xffffffffu, a, o);
        b += __shfl_xor_sync(0xffffffffu, b, o);
    }
    if (lane == 0) { sa[w] = a; sb2[w] = b; }
    __syncthreads();
    a = (threadIdx.x < 8) ? sa[threadIdx.x] : 0.f;
    b = (threadIdx.x < 8) ? sb2[threadIdx.x] : 0.f;
    if (w == 0) {
#pragma unroll
        for (int o = 4; o > 0; o >>= 1) {
            a += __shfl_xor_sync(0xffffffffu, a, o);
            b += __shfl_xor_sync(0xffffffffu, b, o);
        }
    }
}
__device__ __forceinline__ void bn_coef(const float* sums, const float* gamma,
                                        const float* beta, int c, float invN,
                                        float& s, float& t) {
    float mean = sums[c * 2] * invN;
    float var  = sums[c * 2 + 1] * invN - mean * mean;
    s = gamma[c] * rsqrtf(var + EPSV);
    t = beta[c] - mean * s;
}
__device__ __forceinline__ void split4(float a, float b, float c, float d,
                                       uint2& hi, uint2& lo) {
    uint32_t l0, l1;
    uint32_t h0 = pack_hilo(a, b, l0);
    uint32_t h1 = pack_hilo(c, d, l1);
    hi = make_uint2(h0, h1);
    lo = make_uint2(l0, l1);
}

__global__ void __launch_bounds__(256) sumreduce_k(const float* __restrict__ part,
                                                   int P, int CH, float* __restrict__ out) {
    int ch = blockIdx.x;
    float s = 0.f, ss = 0.f;
    for (int p = threadIdx.x; p < P; p += 256) {
        const float* q = part + ((size_t)p * CH + ch) * 2;
        s += q[0]; ss += q[1];
    }
    blockReduce2(s, ss);
    if (threadIdx.x == 0) { out[ch * 2] = s; out[ch * 2 + 1] = ss; }
}

__global__ void __launch_bounds__(256) sumreduceA_k(const float* __restrict__ pA,
                                                    float* __restrict__ out) {
    int ch = blockIdx.x;
    int s_ = ch >> 7, c2 = ch & 127, h = c2 >> 4, il = c2 & 15;
    float s = 0.f, ss = 0.f;
    for (int bb = threadIdx.x; bb < 512; bb += 256) {
        const float* q = pA + (size_t)(bb * 8 + h) * 64 + il * 4 + s_ * 2;
        s += q[0]; ss += q[1];
    }
    blockReduce2(s, ss);
    if (threadIdx.x == 0) { out[ch * 2] = s; out[ch * 2 + 1] = ss; }
}

// ----- T1 --------------------------------------------------------------------
__global__ void __launch_bounds__(256) t1_k(const float* __restrict__ conv1,
                                            const float* __restrict__ sums,
                                            const float* __restrict__ gamma,
                                            const float* __restrict__ beta,
                                            __nv_bfloat16* __restrict__ xh,
                                            __nv_bfloat16* __restrict__ xl) {
    __shared__ float tile[64][65];
    int o = blockIdx.x, b = blockIdx.y;
    float s, t;
    bn_coef(sums, gamma, beta, o, 1.0f / 32768.0f, s, t);
    const float* src = conv1 + (size_t)o * 32768 + b * 4096;
    size_t dsto = (size_t)o * 32768 + b * 4096;
#pragma unroll
    for (int it = 0; it < 4; it++) {
        int f = threadIdx.x + it * 256;
        int h = f >> 4, w4 = (f & 15) * 4;
        float4 v = *(const float4*)(src + h * 64 + w4);
        tile[w4 + 0][h] = fmaxf(fmaf(v.x, s, t), 0.f);
        tile[w4 + 1][h] = fmaxf(fmaf(v.y, s, t), 0.f);
        tile[w4 + 2][h] = fmaxf(fmaf(v.z, s, t), 0.f);
        tile[w4 + 3][h] = fmaxf(fmaf(v.w, s, t), 0.f);
    }
    __syncthreads();
#pragma unroll
    for (int it = 0; it < 4; it++) {
        int f = threadIdx.x + it * 256;
        int w = f >> 4, h4 = (f & 15) * 4;
        uint2 hi, lo;
        split4(tile[w][h4], tile[w][h4 + 1], tile[w][h4 + 2], tile[w][h4 + 3], hi, lo);
        *(uint2*)(xh + dsto + w * 64 + h4) = hi;
        *(uint2*)(xl + dsto + w * 64 + h4) = lo;
    }
}

// ----- closed-form attention BN stats ----------------------------------------
__global__ void __launch_bounds__(256) att_stats_k(const float* __restrict__ qkv,
                                                   const float* __restrict__ rel,
                                                   float* __restrict__ part) {
    __shared__ float Ws[72 * 64];
    __shared__ float Ss[16 * 64];
    int bb = blockIdx.x;
    int tid = threadIdx.x;
    if (tid < 72) {
        int grp = (tid < 36) ? 0 : 1;
        int pr  = (tid < 36) ? tid : tid - 36;
        int i = 0, r = pr;
        while (r >= 8 - i) { r -= 8 - i; i++; }
        int i2 = i + r;
        const float* ra = rel + (grp * 8 + i)  * 127;
        const float* rb = rel + (grp * 8 + i2) * 127;
        float w = 0.f;
        for (int p = 0; p < 64; p++) w = fmaf(ra[p], rb[p], w);
        Ws[tid * 64 + 0] = w;
        for (int d = 1; d < 64; d++) {
            w += ra[d + 63] * rb[d + 63] - ra[d - 1] * rb[d - 1];
            Ws[tid * 64 + d] = w;
        }
    } else if (tid < 88) {
        int rr = tid - 72;
        const float* ra = rel + rr * 127;
        float s = 0.f;
        for (int p = 0; p < 64; p++) s += ra[p];
        Ss[rr * 64 + 0] = s;
        for (int d = 1; d < 64; d++) { s += ra[d + 63] - ra[d - 1]; Ss[rr * 64 + d] = s; }
    }
    __syncthreads();
    int h = tid >> 5, lane = tid & 31;
    float q[8][2], k[8][2];
#pragma unroll
    for (int i = 0; i < 8; i++) {
        const float* pq = qkv + (size_t)(i * 8 + h) * 32768 + bb * 64;
        const float* pk = qkv + (size_t)((8 + i) * 8 + h) * 32768 + bb * 64;
        q[i][0] = pq[lane]; q[i][1] = pq[lane + 32];
        k[i][0] = pk[lane]; k[i][1] = pk[lane + 32];
    }
    float s_qr = 0.f, s_kr = 0.f;
    float Qs[8], Ks[8];
#pragma unroll
    for (int i = 0; i < 8; i++) {
        s_qr = fmaf(q[i][0], Ss[i * 64 + lane], s_qr);
        s_qr = fmaf(q[i][1], Ss[i * 64 + lane + 32], s_qr);
        s_kr = fmaf(k[i][0], Ss[(8 + i) * 64 + lane], s_kr);
        s_kr = fmaf(k[i][1], Ss[(8 + i) * 64 + lane + 32], s_kr);
        Qs[i] = warpSum(q[i][0] + q[i][1]);
        Ks[i] = warpSum(k[i][0] + k[i][1]);
    }
    float s_dots = 0.f;
#pragma unroll
    for (int i = 0; i < 8; i++) s_dots = fmaf(Qs[i], Ks[i], s_dots);

    float ss_qr = 0.f, ss_kr = 0.f, ss_dots = 0.f;
    int pr = 0;
#pragma unroll
    for (int i = 0; i < 8; i++)
#pragma unroll
        for (int i2 = i; i2 < 8; i2++) {
            float coef = (i == i2) ? 1.f : 2.f;
            float pq0 = q[i][0] * q[i2][0], pq1 = q[i][1] * q[i2][1];
            float pk0 = k[i][0] * k[i2][0], pk1 = k[i][1] * k[i2][1];
            ss_qr += coef * (pq0 * Ws[pr * 64 + lane] + pq1 * Ws[pr * 64 + lane + 32]);
            ss_kr += coef * (pk0 * Ws[(36 + pr) * 64 + lane] + pk1 * Ws[(36 + pr) * 64 + lane + 32]);
            float gq = warpSum(pq0 + pq1);
            float gk = warpSum(pk0 + pk1);
            ss_dots = fmaf(coef * gq, gk, ss_dots);
            pr++;
        }
    s_qr = warpSum(s_qr); ss_qr = warpSum(ss_qr);
    s_kr = warpSum(s_kr); ss_kr = warpSum(ss_kr);
    if (lane == 0) {
        int base = bb * 24 + h * 3;
        part[(base + 0) * 2] = s_qr;   part[(base + 0) * 2 + 1] = ss_qr;
        part[(base + 1) * 2] = s_kr;   part[(base + 1) * 2 + 1] = ss_kr;
        part[(base + 2) * 2] = s_dots; part[(base + 2) * 2 + 1] = ss_dots;
    }
}

__global__ void __launch_bounds__(256) attA_fin_k(const float* __restrict__ part,
                                                  const float* __restrict__ ga,
                                                  const float* __restrict__ ba,
                                                  float* __restrict__ scA,
                                                  float* __restrict__ shA) {
    int ch = blockIdx.x;
    float s = 0.f, ss = 0.f;
    for (int bb = threadIdx.x; bb < 512; bb += 256) {
        s  += part[(bb * 24 + ch) * 2];
        ss += part[(bb * 24 + ch) * 2 + 1];
    }
    blockReduce2(s, ss);
    if (threadIdx.x == 0) {
        const float invN = 1.0f / 2097152.0f;
        float mean = s * invN;
        float var  = ss * invN - mean * mean;
        float sc = ga[ch] * rsqrtf(var + EPSV);
        scA[ch] = sc;
        shA[ch] = ba[ch] - mean * sc;
    }
}

// ----- attention mainloop (R10 winner: plain fmaf, conflict-free) ------------
__global__ void __launch_bounds__(256) att_main_k(const float* __restrict__ qkv,
                                                  const float* __restrict__ rel,
                                                  const float* __restrict__ scA,
                                                  const float* __restrict__ shA,
                                                  float* __restrict__ outb,
                                                  float* __restrict__ partA) {
    int bb = blockIdx.x >> 3, h = blockIdx.x & 7;
    __shared__ float qs[8][64], ks[8][64], vs[16][68];
    __shared__ float rqs[8][128], rks[8][128], rvs[16][132];
    __shared__ float attn[64][68];
    __shared__ float stg[16][64];
    int tid = threadIdx.x;
    float sc0 = scA[h * 3 + 0], sh0 = shA[h * 3 + 0];
    float sc1 = scA[h * 3 + 1], sh1 = shA[h * 3 + 1];
    float sc2 = scA[h * 3 + 2], sh2 = shA[h * 3 + 2];

    for (int e = tid; e < 2048; e += 256) {
        int r = e >> 6, d = e & 63;
        float v = qkv[(r * 8 + h) * 32768 + bb * 64 + d];
        if (r < 8) qs[r][d] = v;
        else if (r < 16) ks[r - 8][d] = v;
        else vs[r - 16][d] = v;
    }
    for (int e = tid; e < 32 * 127; e += 256) {
        int r = e / 127, p = e % 127;
        float v = rel[e];
        if (r < 8) rqs[r][p] = v * sc0;
        else if (r < 16) rks[r - 8][p] = v * sc1;
        else rvs[r - 16][p] = v;
    }
    if (tid < 16) {
        rvs[tid][127] = 0.f;
        if (tid < 8) { rqs[tid][127] = 0.f; rks[tid][127] = 0.f; }
    }
    __syncthreads();

    {
        int d0 = (tid >> 4) << 2;
        int j0 = (tid & 15) << 2;
        int pb = d0 - j0 + 60;
        float shsum = sh0 + sh1 + sh2;
        float acc[4][4];
#pragma unroll
        for (int a = 0; a < 4; a++)
#pragma unroll
            for (int b = 0; b < 4; b++) acc[a][b] = shsum;
#pragma unroll
        for (int i = 0; i < 8; i++) {
            float4 qv = *(const float4*)&qs[i][d0];
            float4 kv = *(const float4*)&ks[i][d0];
            float4 kj = *(const float4*)&ks[i][j0];
            float r8q[8], r8k[8];
            *(float4*)&r8q[0] = *(const float4*)&rqs[i][pb];
            *(float4*)&r8q[4] = *(const float4*)&rqs[i][pb + 4];
            *(float4*)&r8k[0] = *(const float4*)&rks[i][pb];
            *(float4*)&r8k[4] = *(const float4*)&rks[i][pb + 4];
            float qa[4] = {qv.x, qv.y, qv.z, qv.w};
            float ka[4] = {kv.x, kv.y, kv.z, kv.w};
            float kja[4] = {kj.x, kj.y, kj.z, kj.w};
            float q2[4];
#pragma unroll
            for (int dd = 0; dd < 4; dd++) q2[dd] = qa[dd] * sc2;
#pragma unroll
            for (int dd = 0; dd < 4; dd++)
#pragma unroll
                for (int jj = 0; jj < 4; jj++) {
                    float t = acc[dd][jj];
                    t = fmaf(qa[dd], r8q[3 + dd - jj], t);
                    t = fmaf(ka[dd], r8k[3 + dd - jj], t);
                    t = fmaf(q2[dd], kja[jj], t);
                    acc[dd][jj] = t;
                }
        }
#pragma unroll
        for (int dd = 0; dd < 4; dd++) {
            float m = fmaxf(fmaxf(acc[dd][0], acc[dd][1]), fmaxf(acc[dd][2], acc[dd][3]));
#pragma unroll
            for (int o = 8; o > 0; o >>= 1) m = fmaxf(m, __shfl_xor_sync(0xffffffffu, m, o));
            float e0 = __expf(acc[dd][0] - m), e1 = __expf(acc[dd][1] - m);
            float e2 = __expf(acc[dd][2] - m), e3 = __expf(acc[dd][3] - m);
            float s = e0 + e1 + e2 + e3;
#pragma unroll
            for (int o = 8; o > 0; o >>= 1) s += __shfl_xor_sync(0xffffffffu, s, o);
            float inv = 1.f / s;
            *(float4*)&attn[d0 + dd][j0] = make_float4(e0 * inv, e1 * inv, e2 * inv, e3 * inv);
        }
    }
    __syncthreads();

    {
        int dg = tid >> 4;
        int ig = (tid >> 2) & 3;
        int jq = tid & 3;
        int d0 = dg << 2, i0 = ig << 2;
        float asv[4][4], asve[4][4];
#pragma unroll
        for (int a = 0; a < 4; a++)
#pragma unroll
            for (int b = 0; b < 4; b++) { asv[a][b] = 0.f; asve[a][b] = 0.f; }

#pragma unroll
        for (int itblk = 0; itblk < 4; itblk++) {
            int j4 = itblk * 16 + jq * 4;
            float a[4][4];
#pragma unroll
            for (int dd = 0; dd < 4; dd++)
                *(float4*)a[dd] = *(const float4*)&attn[d0 + dd][j4];
            int pb = d0 - j4 + 60;
#pragma unroll
            for (int ii = 0; ii < 4; ii++) {
                int i = i0 + ii;
                float vv[4];
                *(float4*)vv = *(const float4*)&vs[i][j4];
                float r8[8];
                *(float4*)&r8[0] = *(const float4*)&rvs[i][pb];
                *(float4*)&r8[4] = *(const float4*)&rvs[i][pb + 4];
#pragma unroll
                for (int dd = 0; dd < 4; dd++)
#pragma unroll
                    for (int jj = 0; jj < 4; jj++) {
                        asv[ii][dd]  = fmaf(a[dd][jj], vv[jj], asv[ii][dd]);
                        asve[ii][dd] = fmaf(a[dd][jj], r8[3 + dd - jj], asve[ii][dd]);
                    }
            }
        }
#pragma unroll
        for (int ii = 0; ii < 4; ii++)
#pragma unroll
            for (int dd = 0; dd < 4; dd++) {
                asv[ii][dd]  += __shfl_xor_sync(0xffffffffu, asv[ii][dd], 1);
                asv[ii][dd]  += __shfl_xor_sync(0xffffffffu, asv[ii][dd], 2);
                asve[ii][dd] += __shfl_xor_sync(0xffffffffu, asve[ii][dd], 1);
                asve[ii][dd] += __shfl_xor_sync(0xffffffffu, asve[ii][dd], 2);
            }
        if (jq == 0) {
#pragma unroll
            for (int ii = 0; ii < 4; ii++) {
                int c2 = h * 16 + i0 + ii;
                size_t o0 = ((size_t)bb * 128 + c2) * 64 + d0;
                *(float4*)&outb[o0] = make_float4(asve[ii][0], asve[ii][1], asve[ii][2], asve[ii][3]);
                *(float4*)&outb[o0 + (size_t)512 * 128 * 64] =
                    make_float4(asv[ii][0], asv[ii][1], asv[ii][2], asv[ii][3]);
                float se = 0.f, qe = 0.f, sv_ = 0.f, qv_ = 0.f;
#pragma unroll
                for (int dd = 0; dd < 4; dd++) {
                    se += asve[ii][dd]; qe = fmaf(asve[ii][dd], asve[ii][dd], qe);
                    sv_ += asv[ii][dd]; qv_ = fmaf(asv[ii][dd], asv[ii][dd], qv_);
                }
                *(float4*)&stg[dg][(i0 + ii) * 4] = make_float4(se, qe, sv_, qv_);
            }
        }
    }
    __syncthreads();
    if (tid < 64) {
        float acc = 0.f;
#pragma unroll
        for (int dg = 0; dg < 16; dg++) acc += stg[dg][tid];
        partA[(size_t)blockIdx.x * 64 + tid] = acc;
    }
}

// ----- T2 --------------------------------------------------------------------
__global__ void __launch_bounds__(256) t2_k(const float* __restrict__ outb,
                                            const float* __restrict__ sums,
                                            const float* __restrict__ gamma,
                                            const float* __restrict__ beta,
                                            __nv_bfloat16* __restrict__ xh,
                                            __nv_bfloat16* __restrict__ xl) {
    __shared__ float tile[64][65];
    int c2 = blockIdx.x, b = blockIdx.y;
    float s0, h0, s1, h1;
    bn_coef(sums, gamma, beta, c2,       1.0f / 32768.0f, s0, h0);
    bn_coef(sums, gamma, beta, 128 + c2, 1.0f / 32768.0f, s1, h1);
    const float* base0 = outb + ((size_t)(b * 64) * 128 + c2) * 64;
    const float* base1 = base0 + (size_t)512 * 128 * 64;
#pragma unroll
    for (int it = 0; it < 4; it++) {
        int f = threadIdx.x + it * 256;
        int w = f >> 4, h4 = (f & 15) * 4;
        float4 v0 = *(const float4*)(base0 + w * 8192 + h4);
        float4 v1 = *(const float4*)(base1 + w * 8192 + h4);
        tile[h4 + 0][w] = fmaf(v0.x, s0, h0) + fmaf(v1.x, s1, h1);
        tile[h4 + 1][w] = fmaf(v0.y, s0, h0) + fmaf(v1.y, s1, h1);
        tile[h4 + 2][w] = fmaf(v0.z, s0, h0) + fmaf(v1.z, s1, h1);
        tile[h4 + 3][w] = fmaf(v0.w, s0, h0) + fmaf(v1.w, s1, h1);
    }
    __syncthreads();
    size_t dsto = (size_t)c2 * 32768 + b * 4096;
#pragma unroll
    for (int it = 0; it < 4; it++) {
        int f = threadIdx.x + it * 256;
        int h = f >> 4, w4 = (f & 15) * 4;
        uint2 hi, lo;
        split4(tile[h][w4], tile[h][w4 + 1], tile[h][w4 + 2], tile[h][w4 + 3], hi, lo);
        *(uint2*)(xh + dsto + h * 64 + w4) = hi;
        *(uint2*)(xl + dsto + h * 64 + w4) = lo;
    }
}

// ----- T3 --------------------------------------------------------------------
__global__ void __launch_bounds__(256) t3_k(const float* __restrict__ outb,
                                            const float* __restrict__ sums,
                                            const float* __restrict__ gamma,
                                            const float* __restrict__ beta,
                                            __nv_bfloat16* __restrict__ xh,
                                            __nv_bfloat16* __restrict__ xl) {
    int g = (blockIdx.x * 256 + threadIdx.x) * 4;
    int w  = g & 63;
    int r  = g >> 6;
    int h  = r & 63;
    int c2 = (r >> 6) & 127;
    int b  = r >> 13;
    int bb = b * 64 + h;
    float s0, h0, s1, h1;
    bn_coef(sums, gamma, beta, c2,       1.0f / 32768.0f, s0, h0);
    bn_coef(sums, gamma, beta, 128 + c2, 1.0f / 32768.0f, s1, h1);
    float4 v0 = *(const float4*)(outb + ((size_t)bb * 128 + c2) * 64 + w);
    float4 v1 = *(const float4*)(outb + ((size_t)(512 + bb) * 128 + c2) * 64 + w);
    float o0 = fmaxf(fmaf(v0.x, s0, h0) + fmaf(v1.x, s1, h1), 0.f);
    float o1 = fmaxf(fmaf(v0.y, s0, h0) + fmaf(v1.y, s1, h1), 0.f);
    float o2 = fmaxf(fmaf(v0.z, s0, h0) + fmaf(v1.z, s1, h1), 0.f);
    float o3 = fmaxf(fmaf(v0.w, s0, h0) + fmaf(v1.w, s1, h1), 0.f);
    uint2 hi, lo;
    split4(o0, o1, o2, o3, hi, lo);
    *(uint2*)(xh + g) = hi;
    *(uint2*)(xl + g) = lo;
}

// ----- final -------------------------------------------------------------------
__global__ void __launch_bounds__(256) final_k(const float* __restrict__ co,
                                               const float* __restrict__ sums,
                                               const float* __restrict__ gamma,
                                               const float* __restrict__ beta,
                                               const float* __restrict__ x_in,
                                               float* __restrict__ out) {
    int g = (blockIdx.x * 256 + threadIdx.x) * 4;
    int o  = (g >> 12) & 255;
    int b  = g >> 20;
    int hw = g & 4095;
    float s, t;
    bn_coef(sums, gamma, beta, o, 1.0f / 32768.0f, s, t);
    float4 c = *(const float4*)(co + (size_t)o * 32768 + b * 4096 + hw);
    float4 x = *(const float4*)(x_in + g);
    float4 y;
    y.x = fmaxf(fmaf(c.x, s, t) + x.x, 0.f);
    y.y = fmaxf(fmaf(c.y, s, t) + x.y, 0.f);
    y.z = fmaxf(fmaf(c.z, s, t) + x.z, 0.f);
    y.w = fmaxf(fmaf(c.w, s, t) + x.w, 0.f);
    *(float4*)(out + g) = y;
}

// ---------------------------------------------------------------------------
extern "C" void kernel_launch(void* const* d_in, const int* in_sizes, int n_in,
                              void* d_out, int out_size) {
    const float* x_in   = (const float*)d_in[0];
    const float* w_in   = (const float*)d_in[1];
    const float* g_in   = (const float*)d_in[2];
    const float* b_in   = (const float*)d_in[3];
    const float* w_out  = (const float*)d_in[4];
    const float* gout   = (const float*)d_in[5];
    const float* bout   = (const float*)d_in[6];
    const float* wqkv_h = (const float*)d_in[7];
    const float* rel_h  = (const float*)d_in[8];
    const float* ga_h   = (const float*)d_in[9];
    const float* ba_h   = (const float*)d_in[10];
    const float* go_h   = (const float*)d_in[11];
    const float* bo_h   = (const float*)d_in[12];
    const float* wqkv_w = (const float*)d_in[13];
    const float* rel_w  = (const float*)d_in[14];
    const float* ga_w   = (const float*)d_in[15];
    const float* ba_w   = (const float*)d_in[16];
    const float* go_w   = (const float*)d_in[17];
    const float* bo_w   = (const float*)d_in[18];
    float* out = (float*)d_out;

    float *conv1, *qkv, *outb, *co, *part, *partG, *partA, *sum, *scA, *shA;
    __nv_bfloat16 *x1h, *x1l, *x2h, *x2l, *x3h, *x3l;
    cudaGetSymbolAddress((void**)&conv1, g_conv1);
    cudaGetSymbolAddress((void**)&qkv,   g_qkv);
    cudaGetSymbolAddress((void**)&outb,  g_outb);
    cudaGetSymbolAddress((void**)&co,    g_co);
    cudaGetSymbolAddress((void**)&part,  g_part);
    cudaGetSymbolAddress((void**)&partG, g_partG);
    cudaGetSymbolAddress((void**)&partA, g_partA);
    cudaGetSymbolAddress((void**)&sum,   g_sum);
    cudaGetSymbolAddress((void**)&scA,   g_scA);
    cudaGetSymbolAddress((void**)&shA,   g_shA);
    cudaGetSymbolAddress((void**)&x1h,   g_x1h);
    cudaGetSymbolAddress((void**)&x1l,   g_x1l);
    cudaGetSymbolAddress((void**)&x2h,   g_x2h);
    cudaGetSymbolAddress((void**)&x2l,   g_x2l);
    cudaGetSymbolAddress((void**)&x3h,   g_x3h);
    cudaGetSymbolAddress((void**)&x3l,   g_x3l);

    const int SMEM_OLD = 71680;
    const int SMEM_CA  = 104448;
    cudaFuncSetAttribute((const void*)gemm_mma<256, 1, true>, cudaFuncAttributeMaxDynamicSharedMemorySize, SMEM_OLD);
    cudaFuncSetAttribute((const void*)gemm_ca<0, false>,      cudaFuncAttributeMaxDynamicSharedMemorySize, SMEM_CA);
    cudaFuncSetAttribute((const void*)gemm_ca<1, true>,       cudaFuncAttributeMaxDynamicSharedMemorySize, SMEM_CA);

    // conv_in (fp32 path, fused BN stats)
    gemm_mma<256, 1, true><<<dim3(256, 1), 128, SMEM_OLD>>>(w_in, x_in, conv1, partG);
    sumreduce_k<<<128, 256>>>(partG, 512, 128, sum);
    t1_k<<<dim3(128, 8), 256>>>(conv1, sum, g_in, b_in, x1h, x1l);

    // axial attention along H
    gemm_ca<0, false><<<dim3(256, 2), 128, SMEM_CA>>>(wqkv_h, x1h, x1l, qkv, nullptr);
    att_stats_k<<<512, 256>>>(qkv, rel_h, part);
    attA_fin_k<<<24, 256>>>(part, ga_h, ba_h, scA, shA);
    att_main_k<<<4096, 256>>>(qkv, rel_h, scA, shA, outb, partA);
    sumreduceA_k<<<256, 256>>>(partA, sum);
    t2_k<<<dim3(128, 8), 256>>>(outb, sum, go_h, bo_h, x2h, x2l);

    // axial attention along W
    gemm_ca<0, false><<<dim3(256, 2), 128, SMEM_CA>>>(wqkv_w, x2h, x2l, qkv, nullptr);
    att_stats_k<<<512, 256>>>(qkv, rel_w, part);
    attA_fin_k<<<24, 256>>>(part, ga_w, ba_w, scA, shA);
    att_main_k<<<4096, 256>>>(qkv, rel_w, scA, shA, outb, partA);
    sumreduceA_k<<<256, 256>>>(partA, sum);
    t3_k<<<4096, 256>>>(outb, sum, go_w, bo_w, x3h, x3l);

    // conv_out (fused BN stats) + residual + relu
    gemm_ca<1, true><<<dim3(256, 2), 128, SMEM_CA>>>(w_out, x3h, x3l, co, partG);
    sumreduce_k<<<256, 256>>>(partG, 512, 256, sum);
    final_k<<<8192, 256>>>(co, sum, gout, bout, x_in, out);
}